// round 15
// baseline (speedup 1.0000x reference)
#include <cuda_runtime.h>
#include <cuda_fp16.h>
#include <math.h>
#include <cstdint>

// Problem constants
#define B_    4
#define H_    768
#define L_    1024
#define N_    4096          // B_*L_
#define M4_   3072          // 4*H_
#define NINP_ 512
#define KC_   1536          // conv K  ([h(t-1); h(t)])
#define KI_   1024          // inject K ([x(t-1); x(t)])
#define NOUT_ 256
#define NLAYER_ 10

#define NBLK_N 32           // n-tiles per layer
#define NBLK_M 24           // m-tiles per layer
#define ITEMS_PER_LAYER (NBLK_N * NBLK_M)     // 768
#define RC_ITEMS 192        // conv-weight repack work items (24576 elems each)
#define TOTAL_ITEMS (NLAYER_ * ITEMS_PER_LAYER + RC_ITEMS) // 7872
#define GRID_PERSIST 296    // 2 CTAs/SM x 148 SMs

// Scratch (device globals; no allocation allowed)
// us layout: [n][mp], mp = y*128 + g*32 + cl  (gate-interleaved, y = ch/32)
__device__ __half g_us2[(size_t)N_ * M4_];
__device__ __half g_ch0[(size_t)N_ * H_];  // c fp16 inter-layer
__device__ __half g_ch1[(size_t)N_ * H_];
__device__ __half g_hh0[(size_t)N_ * H_];  // h fp16 (GEMM A input)
__device__ __half g_hh1[(size_t)N_ * H_];
__device__ __half g_Wc2[(size_t)M4_ * KC_]; // conv W fp16, gate-interleaved rows
__device__ __half g_Wi2[(size_t)M4_ * KI_]; // inject W fp16, gate-interleaved rows
__device__ __half g_Xt[(size_t)N_ * NINP_]; // X fp16, time-major [n][i]
__device__ __half g_z0h[B_ * H_];           // z0 h-part fp16
__device__ float  g_bias[M4_];              // inject_b + conv_b, interleaved index
__device__ float  g_pre0[B_ * M4_];         // layer-0 t==0 corr: W0 @ z0h, interleaved
__device__ unsigned g_ticket;               // work-item ticket
__device__ int    g_rc_done;                // repack items completed
__device__ int    g_cnt[NLAYER_][NBLK_N];   // per-(layer,nblock) completion counts

// ===========================================================================
// Helpers
// ===========================================================================
__device__ __forceinline__ uint32_t smem_u32(const void* p) {
    uint32_t a;
    asm("{ .reg .u64 t; cvta.to.shared.u64 t, %1; cvt.u32.u64 %0, t; }"
        : "=r"(a) : "l"(p));
    return a;
}
__device__ __forceinline__ void cp_async16(uint32_t dst, const void* src) {
    asm volatile("cp.async.cg.shared.global [%0], [%1], 16;" :: "r"(dst), "l"(src));
}
__device__ __forceinline__ void cp_async16_zero(uint32_t dst, const void* src) {
    asm volatile("cp.async.cg.shared.global [%0], [%1], 16, 0;" :: "r"(dst), "l"(src));
}
__device__ __forceinline__ void cp_commit() {
    asm volatile("cp.async.commit_group;");
}
template <int Npend>
__device__ __forceinline__ void cp_wait() {
    asm volatile("cp.async.wait_group %0;" :: "n"(Npend));
}
__device__ __forceinline__ void ldmatrix_x4(uint32_t* r, uint32_t addr) {
    asm volatile("ldmatrix.sync.aligned.m8n8.x4.shared.b16 {%0,%1,%2,%3}, [%4];"
        : "=r"(r[0]), "=r"(r[1]), "=r"(r[2]), "=r"(r[3]) : "r"(addr));
}
__device__ __forceinline__ void mma_f16(float& c0, float& c1, float& c2, float& c3,
                                        uint32_t a0, uint32_t a1, uint32_t a2, uint32_t a3,
                                        uint32_t b0, uint32_t b1) {
    asm volatile(
        "mma.sync.aligned.m16n8k16.row.col.f32.f16.f16.f32 "
        "{%0,%1,%2,%3}, {%4,%5,%6,%7}, {%8,%9}, {%0,%1,%2,%3};"
        : "+f"(c0), "+f"(c1), "+f"(c2), "+f"(c3)
        : "r"(a0), "r"(a1), "r"(a2), "r"(a3), "r"(b0), "r"(b1));
}
__device__ __forceinline__ float tanh_fast(float x) {
    float r;
    asm("tanh.approx.f32 %0, %1;" : "=f"(r) : "f"(x));
    return r;
}
__device__ __forceinline__ int ld_acquire(const int* p) {
    int v;
    asm volatile("ld.acquire.gpu.global.s32 %0, [%1];" : "=r"(v) : "l"(p) : "memory");
    return v;
}

// ===========================================================================
// Fused prep: inject repack + X transpose + z0h + pre0 GEMV + counter init
// Block ranges:
//  [0, 12288)          repack_inj2
//  [12288, 14336)      transpose_x (2048 blocks)
//  [14336, 15872)      gemv_pre0 (1536 blocks, 8 warps each)
//  [15872, 15884)      z0h + counters
// ===========================================================================
#define PREP_INJ_END   12288
#define PREP_TR_END    14336
#define PREP_GEMV_END  15872
#define PREP_TOTAL     15884

__global__ __launch_bounds__(256)
void prep_fused(const float* __restrict__ X,
                const float* __restrict__ z0,
                const float* __restrict__ inject_w,
                const float* __restrict__ inject_b,
                const float* __restrict__ conv_b,
                const float* __restrict__ conv_w) {
    const int bid = blockIdx.x;
    const int tid = threadIdx.x;

    if (bid < PREP_INJ_END) {
        int idx = bid * 256 + tid;
        int mp = idx / KI_;
        int k  = idx - mp * KI_;
        int y  = mp >> 7;
        int g  = (mp >> 5) & 3;
        int cl = mp & 31;
        int m  = g * H_ + y * 32 + cl;
        int tap = (k >= NINP_) ? 1 : 0;
        int i = k - tap * NINP_;
        g_Wi2[idx] = __float2half_rn(inject_w[m * (NINP_ * 2) + i * 2 + tap]);
        if (k == 0) g_bias[mp] = inject_b[m] + conv_b[m];
        return;
    }
    if (bid < PREP_TR_END) {
        __shared__ float tile[32][33];
        int tb = bid - PREP_INJ_END;
        int bx = tb & 31;           // t0 block
        int by = (tb >> 5) & 15;    // i0 block
        int bz = tb >> 9;           // batch
        int i0 = by * 32;
        int t0 = bx * 32;
        int tx = tid & 31, ty = tid >> 5;
#pragma unroll
        for (int j = 0; j < 32; j += 8)
            tile[ty + j][tx] = X[(size_t)(bz * NINP_ + i0 + ty + j) * L_ + t0 + tx];
        __syncthreads();
#pragma unroll
        for (int j = 0; j < 32; j += 8)
            g_Xt[(size_t)(bz * L_ + t0 + ty + j) * NINP_ + i0 + tx] =
                __float2half_rn(tile[tx][ty + j]);
        return;
    }
    if (bid < PREP_GEMV_END) {
        int w = (bid - PREP_TR_END) * 8 + (tid >> 5);
        int lane = tid & 31;
        if (w >= M4_ * B_) return;
        int m = w >> 2;
        int b = w & 3;
        float s = 0.0f;
        for (int i = lane; i < H_; i += 32)
            s += conv_w[(size_t)m * (2 * H_) + 2 * i] * z0[b * (2 * H_) + i];
#pragma unroll
        for (int o = 16; o; o >>= 1) s += __shfl_xor_sync(0xFFFFFFFFu, s, o);
        if (lane == 0) {
            int g = m / H_;
            int r = m - g * H_;
            int mp = (r >> 5) * 128 + g * 32 + (r & 31);
            g_pre0[b * M4_ + mp] = s;
        }
        return;
    }
    {
        int idx = (bid - PREP_GEMV_END) * 256 + tid;
        if (idx < B_ * H_) {
            int b = idx / H_, ch = idx - b * H_;
            g_z0h[idx] = __float2half_rn(z0[b * (2 * H_) + ch]);
        }
        if (idx == 0) { g_ticket = 0; g_rc_done = 0; }
        if (idx < NLAYER_ * NBLK_N) ((int*)g_cnt)[idx] = 0;
    }
}

// ===========================================================================
// Persistent mega-kernel: conv-weight repack + all layers in one launch.
// Tickets: [0,768) layer-0 tiles; [768,960) repack items; [960,...) layers 1..9.
// ===========================================================================
#define BK      64
#define KS      72                       // padded row stride (halfs), 144B
#define STG_A   (128 * KS)
#define STG_SZ  (2 * 128 * KS)
#define NSTAGE  3
#define SMEM_BYTES (NSTAGE * STG_SZ * 2) // 110592
#define USS     136                      // us_s row stride in halfs
#define PS      136                      // pre_s row stride in floats
#define PRE_OFF 4352                     // float offset of pre_s
#define RC_ELEMS 24576                   // elems per repack item (M4*KC/192)

__global__ __launch_bounds__(256, 2)
void gemm_mega(const float* __restrict__ z0, float* __restrict__ out,
               const float* __restrict__ conv_w) {
    extern __shared__ __half smh[];
    __shared__ unsigned sm_w;

    const int tid  = threadIdx.x;
    const int wid  = tid >> 5;
    const int lane = tid & 31;
    const int grp  = lane >> 2;
    const int qid  = lane & 3;
    const int wn = (wid >> 2) * 64;
    const int wm = (wid & 3) * 32;
    const uint32_t sbase = smem_u32(smh);
    const int lrow = lane & 15;
    const int lcol = (lane >> 4) << 3;
    const int q  = tid & 7;
    const int nl = tid >> 3;

    for (;;) {
        if (tid == 0) sm_w = atomicAdd(&g_ticket, 1u);
        __syncthreads();
        const unsigned w = sm_w;
        if (w >= TOTAL_ITEMS) return;

        // ---- repack work items (tickets 768..959) ----
        if (w >= ITEMS_PER_LAYER && w < ITEMS_PER_LAYER + RC_ITEMS) {
            int base = (int)(w - ITEMS_PER_LAYER) * RC_ELEMS;
#pragma unroll 4
            for (int j = 0; j < RC_ELEMS / 256; j++) {
                int idx = base + tid + j * 256;
                int mp = idx / KC_;
                int k  = idx - mp * KC_;
                int y  = mp >> 7;
                int g  = (mp >> 5) & 3;
                int cl = mp & 31;
                int m  = g * H_ + y * 32 + cl;
                int tap = (k >= H_) ? 1 : 0;
                int i = k - tap * H_;
                g_Wc2[idx] = __float2half_rn(conv_w[m * (H_ * 2) + i * 2 + tap]);
            }
            __syncthreads();
            if (tid == 0) { __threadfence(); atomicAdd(&g_rc_done, 1); }
            continue;
        }

        const unsigned ww = (w < ITEMS_PER_LAYER) ? w : w - RC_ITEMS;
        const int l    = ww / ITEMS_PER_LAYER;
        const int r_   = ww - l * ITEMS_PER_LAYER;
        const int iblk = r_ / NBLK_M;
        const int mblk = r_ - iblk * NBLK_M;
        const int n0 = iblk * 128;
        const int m0 = mblk * 128;
        const bool inj  = (l == 0);
        const bool last = (l == NLAYER_ - 1);
        const int  rd   = l & 1;

        const __half* __restrict__ Asrc = inj ? g_Xt : (rd ? g_hh1 : g_hh0);
        const __half* __restrict__ Bw   = inj ? g_Wi2 : g_Wc2;
        const int KTOT  = inj ? KI_ : KC_;
        const int KHALF = inj ? NINP_ : H_;
        const int NKT   = KTOT / BK;

#define LOAD_STAGE_B(S, K0)                                                      \
    do {                                                                         \
        const int _k0 = (K0);                                                    \
        const uint32_t boff = ((S) % NSTAGE) * STG_SZ + STG_A;                   \
        _Pragma("unroll")                                                        \
        for (int j = 0; j < 4; j++) {                                            \
            int idx = tid + j * 256;                                             \
            int r  = idx >> 3;                                                   \
            int c8 = idx & 7;                                                    \
            int kk = _k0 + c8 * 8;                                               \
            uint32_t dst = sbase + (boff + r * KS + c8 * 8) * 2;                 \
            cp_async16(dst, Bw + (size_t)(m0 + r) * KTOT + kk);                  \
        }                                                                        \
        cp_commit();                                                             \
    } while (0)

#define LOAD_STAGE_A(S, K0)                                                      \
    do {                                                                         \
        const int _k0 = (K0);                                                    \
        const uint32_t aoff = ((S) % NSTAGE) * STG_SZ;                           \
        _Pragma("unroll")                                                        \
        for (int j = 0; j < 4; j++) {                                            \
            int idx = tid + j * 256;                                             \
            int r  = idx >> 3;                                                   \
            int c8 = idx & 7;                                                    \
            int kk = _k0 + c8 * 8;                                               \
            int n = n0 + r;                                                      \
            int t = n & (L_ - 1);                                                \
            int b = n >> 10;                                                     \
            uint32_t dst = sbase + (aoff + r * KS + c8 * 8) * 2;                 \
            if (kk < KHALF) {                                                    \
                if (t == 0) {                                                    \
                    if (inj) cp_async16_zero(dst, Asrc);                         \
                    else cp_async16(dst, g_z0h + b * H_ + kk);                   \
                } else {                                                         \
                    cp_async16(dst, Asrc + (size_t)(n - 1) * KHALF + kk);        \
                }                                                                \
            } else {                                                             \
                cp_async16(dst, Asrc + (size_t)n * KHALF + (kk - KHALF));        \
            }                                                                    \
        }                                                                        \
        cp_commit();                                                             \
    } while (0)

#define LOAD_STAGE_AB(S, K0)                                                     \
    do {                                                                         \
        const int _k0 = (K0);                                                    \
        const uint32_t aoff = ((S) % NSTAGE) * STG_SZ;                           \
        const uint32_t boff = aoff + STG_A;                                      \
        _Pragma("unroll")                                                        \
        for (int j = 0; j < 4; j++) {                                            \
            int idx = tid + j * 256;                                             \
            int r  = idx >> 3;                                                   \
            int c8 = idx & 7;                                                    \
            int kk = _k0 + c8 * 8;                                               \
            {                                                                    \
                int n = n0 + r;                                                  \
                int t = n & (L_ - 1);                                            \
                int b = n >> 10;                                                 \
                uint32_t dst = sbase + (aoff + r * KS + c8 * 8) * 2;             \
                if (kk < KHALF) {                                                \
                    if (t == 0) {                                                \
                        if (inj) cp_async16_zero(dst, Asrc);                     \
                        else cp_async16(dst, g_z0h + b * H_ + kk);               \
                    } else {                                                     \
                        cp_async16(dst, Asrc + (size_t)(n - 1) * KHALF + kk);    \
                    }                                                            \
                } else {                                                         \
                    cp_async16(dst, Asrc + (size_t)n * KHALF + (kk - KHALF));    \
                }                                                                \
            }                                                                    \
            {                                                                    \
                uint32_t dst = sbase + (boff + r * KS + c8 * 8) * 2;             \
                cp_async16(dst, Bw + (size_t)(m0 + r) * KTOT + kk);              \
            }                                                                    \
        }                                                                        \
        cp_commit();                                                             \
    } while (0)

        // wait for conv-weight repack before touching g_Wc2
        if (tid == 0 && l > 0) {
            while (ld_acquire(&g_rc_done) < RC_ITEMS) __nanosleep(64);
        }
        if (l > 0) __syncthreads();

        // prefetch weight stages (no h/c dependency), then wait for producers
        LOAD_STAGE_B(0, 0);
        LOAD_STAGE_B(1, BK);
        if (tid == 0 && l > 0) {
            int lo = (iblk > 0) ? iblk - 1 : 0;
            int hi = (iblk < NBLK_N - 1) ? iblk + 1 : NBLK_N - 1;
            for (int ii = lo; ii <= hi; ii++)
                while (ld_acquire(&g_cnt[l - 1][ii]) < NBLK_M) __nanosleep(64);
        }
        __syncthreads();
        LOAD_STAGE_A(0, 0);
        LOAD_STAGE_A(1, BK);

        float acc[4][4][4];
#pragma unroll
        for (int i = 0; i < 4; i++)
#pragma unroll
            for (int j = 0; j < 4; j++)
#pragma unroll
                for (int e = 0; e < 4; e++) acc[i][j][e] = 0.0f;

#pragma unroll 1
        for (int kt = 0; kt < NKT; kt++) {
            cp_wait<NSTAGE - 2>();
            __syncthreads();

            const int sf = kt + NSTAGE - 1;
            if (sf < NKT) LOAD_STAGE_AB(sf, sf * BK);
            else cp_commit();

            const uint32_t a_base = sbase + (uint32_t)((kt % NSTAGE) * STG_SZ) * 2;
            const uint32_t b_base = a_base + STG_A * 2;

#pragma unroll
            for (int ks = 0; ks < BK; ks += 16) {
                uint32_t af[4][4];
                uint32_t bf[2][4];
#pragma unroll
                for (int fi = 0; fi < 4; fi++) {
                    uint32_t addr = a_base +
                        (uint32_t)((wn + fi * 16 + lrow) * KS + ks + lcol) * 2;
                    ldmatrix_x4(af[fi], addr);
                }
#pragma unroll
                for (int fh = 0; fh < 2; fh++) {
                    uint32_t addr = b_base +
                        (uint32_t)((wm + fh * 16 + lrow) * KS + ks + lcol) * 2;
                    ldmatrix_x4(bf[fh], addr);
                }
#pragma unroll
                for (int fi = 0; fi < 4; fi++) {
#pragma unroll
                    for (int fh = 0; fh < 2; fh++) {
#pragma unroll
                        for (int s2 = 0; s2 < 2; s2++) {
                            int fj = fh * 2 + s2;
                            mma_f16(acc[fi][fj][0], acc[fi][fj][1],
                                    acc[fi][fj][2], acc[fi][fj][3],
                                    af[fi][0], af[fi][1], af[fi][2], af[fi][3],
                                    bf[fh][s2], bf[fh][s2 + 2]);
                        }
                    }
                }
            }
        }

        // ---------------- epilogue ----------------
        __half* us_s  = smh;
        float*  pre_s = (float*)smh + PRE_OFF;
        const int chbase = mblk * 32;

        if (inj) {
#pragma unroll
            for (int fi = 0; fi < 4; fi++) {
#pragma unroll
                for (int fj = 0; fj < 4; fj++) {
                    int n1  = n0 + wn + fi * 16 + grp;
                    int col = wm + fj * 8 + qid * 2;
                    float b0 = g_bias[m0 + col], b1 = g_bias[m0 + col + 1];
                    acc[fi][fj][0] += b0; acc[fi][fj][1] += b1;
                    acc[fi][fj][2] += b0; acc[fi][fj][3] += b1;
                    *(__half2*)(g_us2 + (size_t)n1 * M4_ + m0 + col) =
                        __floats2half2_rn(acc[fi][fj][0], acc[fi][fj][1]);
                    *(__half2*)(g_us2 + (size_t)(n1 + 8) * M4_ + m0 + col) =
                        __floats2half2_rn(acc[fi][fj][2], acc[fi][fj][3]);
                }
            }
#pragma unroll
            for (int p = 0; p < 2; p++) {
                __syncthreads();
                if ((wid >> 2) == p) {
#pragma unroll
                    for (int fi = 0; fi < 4; fi++) {
#pragma unroll
                        for (int fj = 0; fj < 4; fj++) {
                            int r0   = fi * 16 + grp;
                            int cidx = wm + fj * 8 + qid * 2;
                            *(float2*)&pre_s[r0 * PS + cidx] =
                                make_float2(acc[fi][fj][0], acc[fi][fj][1]);
                            *(float2*)&pre_s[(r0 + 8) * PS + cidx] =
                                make_float2(acc[fi][fj][2], acc[fi][fj][3]);
                        }
                    }
                }
                __syncthreads();
#pragma unroll
                for (int it = 0; it < 2; it++) {
                    int row = nl + it * 32;
                    int n = n0 + p * 64 + row;
                    int t = n & (L_ - 1);
                    int b = n >> 10;
                    int ch = chbase + q * 4;

                    float pi[4], po[4], pg[4], pf[4], cprev[4];
#pragma unroll
                    for (int e = 0; e < 4; e++) {
                        pi[e] = pre_s[row * PS + 0 * 32 + q * 4 + e];
                        po[e] = pre_s[row * PS + 1 * 32 + q * 4 + e];
                        pg[e] = pre_s[row * PS + 2 * 32 + q * 4 + e];
                        pf[e] = pre_s[row * PS + 3 * 32 + q * 4 + e];
                        cprev[e] = 0.0f;
                    }
                    if (t == 0) {
#pragma unroll
                        for (int e = 0; e < 4; e++) {
                            pi[e] += g_pre0[b * M4_ + m0 + 0 * 32 + q * 4 + e];
                            po[e] += g_pre0[b * M4_ + m0 + 1 * 32 + q * 4 + e];
                            pg[e] += g_pre0[b * M4_ + m0 + 2 * 32 + q * 4 + e];
                            pf[e] += g_pre0[b * M4_ + m0 + 3 * 32 + q * 4 + e];
                            cprev[e] = z0[b * (2 * H_) + H_ + ch + e];
                        }
                    }
                    __half hh[4], cc[4];
#pragma unroll
                    for (int e = 0; e < 4; e++) {
                        float si = 1.0f / (1.0f + __expf(-pi[e]));
                        float so = 1.0f / (1.0f + __expf(-po[e]));
                        float sf = 1.0f / (1.0f + __expf(-pf[e]));
                        float tg = tanh_fast(pg[e]);
                        float c = sf * cprev[e] + si * tg;
                        float h = so * tanh_fast(c);
                        hh[e] = __float2half_rn(h);
                        cc[e] = __float2half_rn(c);
                    }
                    *(__half2*)(g_hh1 + (size_t)n * H_ + ch)     = __halves2half2(hh[0], hh[1]);
                    *(__half2*)(g_hh1 + (size_t)n * H_ + ch + 2) = __halves2half2(hh[2], hh[3]);
                    *(__half2*)(g_ch1 + (size_t)n * H_ + ch)     = __halves2half2(cc[0], cc[1]);
                    *(__half2*)(g_ch1 + (size_t)n * H_ + ch + 2) = __halves2half2(cc[2], cc[3]);
                }
            }
        } else {
            const __half* __restrict__ cpb = rd ? g_ch1 : g_ch0;
            __half* __restrict__ cn  = rd ? g_ch0 : g_ch1;
            __half* __restrict__ hhn = rd ? g_hh0 : g_hh1;

#pragma unroll
            for (int p = 0; p < 2; p++) {
                __syncthreads();
#pragma unroll
                for (int j = 0; j < 4; j++) {
                    int id = tid + j * 256;
                    int row = id >> 4;
                    int c   = id & 15;
                    int n = n0 + p * 64 + row;
                    cp_async16(sbase + (uint32_t)(row * USS + c * 8) * 2,
                               g_us2 + (size_t)n * M4_ + m0 + c * 8);
                }
                cp_commit();

                if ((wid >> 2) == p) {
#pragma unroll
                    for (int fi = 0; fi < 4; fi++) {
#pragma unroll
                        for (int fj = 0; fj < 4; fj++) {
                            int r0   = fi * 16 + grp;
                            int cidx = wm + fj * 8 + qid * 2;
                            *(float2*)&pre_s[r0 * PS + cidx] =
                                make_float2(acc[fi][fj][0], acc[fi][fj][1]);
                            *(float2*)&pre_s[(r0 + 8) * PS + cidx] =
                                make_float2(acc[fi][fj][2], acc[fi][fj][3]);
                        }
                    }
                }
                cp_wait<0>();
                __syncthreads();

#pragma unroll
                for (int it = 0; it < 2; it++) {
                    int row = nl + it * 32;
                    int n = n0 + p * 64 + row;
                    int t = n & (L_ - 1);
                    int b = n >> 10;
                    int ch = chbase + q * 4;

                    float4 pi4 = *(const float4*)&pre_s[row * PS + 0 * 32 + q * 4];
                    float4 po4 = *(const float4*)&pre_s[row * PS + 1 * 32 + q * 4];
                    float4 pg4 = *(const float4*)&pre_s[row * PS + 2 * 32 + q * 4];
                    float4 pf4 = *(const float4*)&pre_s[row * PS + 3 * 32 + q * 4];

                    const __half* ur = us_s + row * USS + q * 4;
                    float2 uiA = __half22float2(*(const __half2*)(ur + 0 * 32));
                    float2 uiB = __half22float2(*(const __half2*)(ur + 0 * 32 + 2));
                    float2 uoA = __half22float2(*(const __half2*)(ur + 1 * 32));
                    float2 uoB = __half22float2(*(const __half2*)(ur + 1 * 32 + 2));
                    float2 ugA = __half22float2(*(const __half2*)(ur + 2 * 32));
                    float2 ugB = __half22float2(*(const __half2*)(ur + 2 * 32 + 2));
                    float2 ufA = __half22float2(*(const __half2*)(ur + 3 * 32));
                    float2 ufB = __half22float2(*(const __half2*)(ur + 3 * 32 + 2));
                    float ui[4] = {uiA.x, uiA.y, uiB.x, uiB.y};
                    float uo[4] = {uoA.x, uoA.y, uoB.x, uoB.y};
                    float ug[4] = {ugA.x, ugA.y, ugB.x, ugB.y};
                    float uf[4] = {ufA.x, ufA.y, ufB.x, ufB.y};

                    float cpl[4];
                    if (t == 0) {
                        float4 zc = *(const float4*)(z0 + b * (2 * H_) + H_ + ch);
                        cpl[0] = zc.x; cpl[1] = zc.y; cpl[2] = zc.z; cpl[3] = zc.w;
                    } else {
                        float2 cA = __half22float2(*(const __half2*)(cpb + (size_t)(n - 1) * H_ + ch));
                        float2 cB = __half22float2(*(const __half2*)(cpb + (size_t)(n - 1) * H_ + ch + 2));
                        cpl[0] = cA.x; cpl[1] = cA.y; cpl[2] = cB.x; cpl[3] = cB.y;
                    }

                    const float* pip = (const float*)&pi4;
                    const float* pop = (const float*)&po4;
                    const float* pgp = (const float*)&pg4;
                    const float* pfp = (const float*)&pf4;

                    float4 hv, cv;
                    float* hvp = (float*)&hv;
                    float* cvp = (float*)&cv;
#pragma unroll
                    for (int e = 0; e < 4; e++) {
                        float pi = pip[e] + ui[e];
                        float po = pop[e] + uo[e];
                        float pg = pgp[e] + ug[e];
                        float pf = pfp[e] + uf[e];
                        float si = 1.0f / (1.0f + __expf(-pi));
                        float so = 1.0f / (1.0f + __expf(-po));
                        float sf = 1.0f / (1.0f + __expf(-pf));
                        float tg = tanh_fast(pg);
                        float c = sf * cpl[e] + si * tg;
                        float h = so * tanh_fast(c);
                        hvp[e] = h;
                        cvp[e] = c;
                    }
                    if (last) {
                        if (chbase >= H_ - NOUT_) {
                            *(float4*)(out + (size_t)n * NOUT_ + (ch - (H_ - NOUT_))) = hv;
                        }
                        if (t == L_ - 1) {
                            const size_t tot = (size_t)B_ * L_ * NOUT_;
                            *(float4*)(out + tot + b * (2 * H_) + ch)      = hv;
                            *(float4*)(out + tot + b * (2 * H_) + H_ + ch) = cv;
                        }
                    } else {
                        __half2 h01 = __floats2half2_rn(hvp[0], hvp[1]);
                        __half2 h23 = __floats2half2_rn(hvp[2], hvp[3]);
                        __half2 c01 = __floats2half2_rn(cvp[0], cvp[1]);
                        __half2 c23 = __floats2half2_rn(cvp[2], cvp[3]);
                        *(__half2*)(hhn + (size_t)n * H_ + ch)     = h01;
                        *(__half2*)(hhn + (size_t)n * H_ + ch + 2) = h23;
                        *(__half2*)(cn + (size_t)n * H_ + ch)      = c01;
                        *(__half2*)(cn + (size_t)n * H_ + ch + 2)  = c23;
                    }
                }
            }
        }

        // publish completion
        __syncthreads();
        if (tid == 0) {
            __threadfence();
            atomicAdd(&g_cnt[l][iblk], 1);
        }
#undef LOAD_STAGE_AB
#undef LOAD_STAGE_A
#undef LOAD_STAGE_B
    }
}

// ===========================================================================
extern "C" void kernel_launch(void* const* d_in, const int* in_sizes, int n_in,
                              void* d_out, int out_size) {
    const float* X        = (const float*)d_in[0];
    const float* z0       = (const float*)d_in[1];
    const float* inject_w = (const float*)d_in[2];
    const float* inject_b = (const float*)d_in[3];
    const float* conv_w   = (const float*)d_in[4];
    const float* conv_b   = (const float*)d_in[5];
    float* out = (float*)d_out;

    cudaFuncSetAttribute(gemm_mega,
                         cudaFuncAttributeMaxDynamicSharedMemorySize, SMEM_BYTES);

    prep_fused<<<PREP_TOTAL, 256>>>(X, z0, inject_w, inject_b, conv_b, conv_w);
    gemm_mega<<<GRID_PERSIST, 256, SMEM_BYTES>>>(z0, out, conv_w);
}

// round 16
// speedup vs baseline: 1.0259x; 1.0259x over previous
#include <cuda_runtime.h>
#include <cuda_fp16.h>
#include <math.h>
#include <cstdint>

// Problem constants
#define B_    4
#define H_    768
#define L_    1024
#define N_    4096          // B_*L_
#define M4_   3072          // 4*H_
#define NINP_ 512
#define KC_   1536          // conv K  ([h(t-1); h(t)])
#define KI_   1024          // inject K ([x(t-1); x(t)])
#define NOUT_ 256
#define NLAYER_ 10

#define NBLK_N 32           // n-tiles per layer
#define NBLK_M 24           // m-tiles per layer
#define ITEMS_PER_LAYER (NBLK_N * NBLK_M)       // 768
#define TOTAL_ITEMS (NLAYER_ * ITEMS_PER_LAYER) // 7680
#define GRID_PERSIST 296    // 2 CTAs/SM x 148 SMs

// Scratch (device globals; no allocation allowed)
// us layout: [n][mp], mp = y*128 + g*32 + cl  (gate-interleaved, y = ch/32)
__device__ __half g_us2[(size_t)N_ * M4_];
__device__ __half g_ch0[(size_t)N_ * H_];  // c fp16 inter-layer
__device__ __half g_ch1[(size_t)N_ * H_];
__device__ __half g_hh0[(size_t)N_ * H_];  // h fp16 (GEMM A input)
__device__ __half g_hh1[(size_t)N_ * H_];
__device__ __half g_Wc2[(size_t)M4_ * KC_]; // conv W fp16, gate-interleaved rows
__device__ __half g_Wi2[(size_t)M4_ * KI_]; // inject W fp16, gate-interleaved rows
__device__ __half g_Xt[(size_t)N_ * NINP_]; // X fp16, time-major [n][i]
__device__ __half g_z0h[B_ * H_];           // z0 h-part fp16
__device__ float  g_bias[M4_];              // inject_b + conv_b, interleaved index
__device__ float  g_pre0[B_ * M4_];         // layer-0 t==0 corr: W0 @ z0h, interleaved
__device__ unsigned g_ticket;               // work-item ticket
__device__ int    g_cnt[NLAYER_][NBLK_N];   // per-(layer,nblock) completion counts

// ===========================================================================
// Helpers
// ===========================================================================
__device__ __forceinline__ uint32_t smem_u32(const void* p) {
    uint32_t a;
    asm("{ .reg .u64 t; cvta.to.shared.u64 t, %1; cvt.u32.u64 %0, t; }"
        : "=r"(a) : "l"(p));
    return a;
}
__device__ __forceinline__ void cp_async16(uint32_t dst, const void* src) {
    asm volatile("cp.async.cg.shared.global [%0], [%1], 16;" :: "r"(dst), "l"(src));
}
__device__ __forceinline__ void cp_async16_zero(uint32_t dst, const void* src) {
    asm volatile("cp.async.cg.shared.global [%0], [%1], 16, 0;" :: "r"(dst), "l"(src));
}
__device__ __forceinline__ void cp_commit() {
    asm volatile("cp.async.commit_group;");
}
template <int Npend>
__device__ __forceinline__ void cp_wait() {
    asm volatile("cp.async.wait_group %0;" :: "n"(Npend));
}
__device__ __forceinline__ void ldmatrix_x4(uint32_t* r, uint32_t addr) {
    asm volatile("ldmatrix.sync.aligned.m8n8.x4.shared.b16 {%0,%1,%2,%3}, [%4];"
        : "=r"(r[0]), "=r"(r[1]), "=r"(r[2]), "=r"(r[3]) : "r"(addr));
}
__device__ __forceinline__ void mma_f16(float& c0, float& c1, float& c2, float& c3,
                                        uint32_t a0, uint32_t a1, uint32_t a2, uint32_t a3,
                                        uint32_t b0, uint32_t b1) {
    asm volatile(
        "mma.sync.aligned.m16n8k16.row.col.f32.f16.f16.f32 "
        "{%0,%1,%2,%3}, {%4,%5,%6,%7}, {%8,%9}, {%0,%1,%2,%3};"
        : "+f"(c0), "+f"(c1), "+f"(c2), "+f"(c3)
        : "r"(a0), "r"(a1), "r"(a2), "r"(a3), "r"(b0), "r"(b1));
}
__device__ __forceinline__ float tanh_fast(float x) {
    float r;
    asm("tanh.approx.f32 %0, %1;" : "=f"(r) : "f"(x));
    return r;
}
__device__ __forceinline__ int ld_acquire(const int* p) {
    int v;
    asm volatile("ld.acquire.gpu.global.s32 %0, [%1];" : "=r"(v) : "l"(p) : "memory");
    return v;
}

// ===========================================================================
// Fused prep: conv repack + inject repack + X transpose + pre0 GEMV + z0h/init
// Block ranges:
//  [0, 18432)          repack conv (M4*KC/256)
//  [18432, 30720)      repack inject
//  [30720, 32768)      transpose_x (2048 blocks)
//  [32768, 34304)      gemv_pre0 (1536 blocks, 8 warps each)
//  [34304, 34316)      z0h + counters
// ===========================================================================
#define PREP_CONV_END  18432
#define PREP_INJ_END   30720
#define PREP_TR_END    32768
#define PREP_GEMV_END  34304
#define PREP_TOTAL     34316

__global__ __launch_bounds__(256)
void prep_fused(const float* __restrict__ X,
                const float* __restrict__ z0,
                const float* __restrict__ inject_w,
                const float* __restrict__ inject_b,
                const float* __restrict__ conv_b,
                const float* __restrict__ conv_w) {
    const int bid = blockIdx.x;
    const int tid = threadIdx.x;

    if (bid < PREP_CONV_END) {
        int idx = bid * 256 + tid;
        int mp = idx / KC_;
        int k  = idx - mp * KC_;
        int y  = mp >> 7;
        int g  = (mp >> 5) & 3;
        int cl = mp & 31;
        int m  = g * H_ + y * 32 + cl;
        int tap = (k >= H_) ? 1 : 0;
        int i = k - tap * H_;
        g_Wc2[idx] = __float2half_rn(conv_w[m * (H_ * 2) + i * 2 + tap]);
        return;
    }
    if (bid < PREP_INJ_END) {
        int idx = (bid - PREP_CONV_END) * 256 + tid;
        int mp = idx / KI_;
        int k  = idx - mp * KI_;
        int y  = mp >> 7;
        int g  = (mp >> 5) & 3;
        int cl = mp & 31;
        int m  = g * H_ + y * 32 + cl;
        int tap = (k >= NINP_) ? 1 : 0;
        int i = k - tap * NINP_;
        g_Wi2[idx] = __float2half_rn(inject_w[m * (NINP_ * 2) + i * 2 + tap]);
        if (k == 0) g_bias[mp] = inject_b[m] + conv_b[m];
        return;
    }
    if (bid < PREP_TR_END) {
        __shared__ float tile[32][33];
        int tb = bid - PREP_INJ_END;
        int bx = tb & 31;
        int by = (tb >> 5) & 15;
        int bz = tb >> 9;
        int i0 = by * 32;
        int t0 = bx * 32;
        int tx = tid & 31, ty = tid >> 5;
#pragma unroll
        for (int j = 0; j < 32; j += 8)
            tile[ty + j][tx] = X[(size_t)(bz * NINP_ + i0 + ty + j) * L_ + t0 + tx];
        __syncthreads();
#pragma unroll
        for (int j = 0; j < 32; j += 8)
            g_Xt[(size_t)(bz * L_ + t0 + ty + j) * NINP_ + i0 + tx] =
                __float2half_rn(tile[tx][ty + j]);
        return;
    }
    if (bid < PREP_GEMV_END) {
        int w = (bid - PREP_TR_END) * 8 + (tid >> 5);
        int lane = tid & 31;
        if (w >= M4_ * B_) return;
        int m = w >> 2;
        int b = w & 3;
        float s = 0.0f;
        for (int i = lane; i < H_; i += 32)
            s += conv_w[(size_t)m * (2 * H_) + 2 * i] * z0[b * (2 * H_) + i];
#pragma unroll
        for (int o = 16; o; o >>= 1) s += __shfl_xor_sync(0xFFFFFFFFu, s, o);
        if (lane == 0) {
            int g = m / H_;
            int r = m - g * H_;
            int mp = (r >> 5) * 128 + g * 32 + (r & 31);
            g_pre0[b * M4_ + mp] = s;
        }
        return;
    }
    {
        int idx = (bid - PREP_GEMV_END) * 256 + tid;
        if (idx < B_ * H_) {
            int b = idx / H_, ch = idx - b * H_;
            g_z0h[idx] = __float2half_rn(z0[b * (2 * H_) + ch]);
        }
        if (idx == 0) g_ticket = 0;
        if (idx < NLAYER_ * NBLK_N) ((int*)g_cnt)[idx] = 0;
    }
}

// ===========================================================================
// Tile worker (compile-time KTOT/INJ -> constant-folded address math)
// ===========================================================================
#define BK      64
#define KS      72                       // padded row stride (halfs), 144B
#define STG_A   (128 * KS)
#define STG_SZ  (2 * 128 * KS)
#define NSTAGE  3
#define SMEM_BYTES (NSTAGE * STG_SZ * 2) // 110592
#define USS     136                      // us_s row stride in halfs
#define PS      136                      // pre_s row stride in floats
#define PRE_OFF 4352                     // float offset of pre_s

template <int KTOT, bool INJ>
__device__ __forceinline__ void do_tile(
    __half* smh, uint32_t sbase,
    const float* __restrict__ z0, float* __restrict__ out,
    int n0, int m0, int iblk, int l, bool last, int rd) {

    constexpr int KHALF = KTOT / 2;
    constexpr int NKT = KTOT / BK;

    const __half* __restrict__ Asrc = INJ ? g_Xt : (rd ? g_hh1 : g_hh0);
    const __half* __restrict__ Bw   = INJ ? g_Wi2 : g_Wc2;

    const int tid  = threadIdx.x;
    const int wid  = tid >> 5;
    const int lane = tid & 31;
    const int grp  = lane >> 2;
    const int qid  = lane & 3;
    const int wn = (wid >> 2) * 64;
    const int wm = (wid & 3) * 32;
    const int lrow = lane & 15;
    const int lcol = (lane >> 4) << 3;
    const int q  = tid & 7;
    const int nl = tid >> 3;

#define LOAD_STAGE_B(S, K0)                                                      \
    do {                                                                         \
        const int _k0 = (K0);                                                    \
        const uint32_t boff = ((S) % NSTAGE) * STG_SZ + STG_A;                   \
        _Pragma("unroll")                                                        \
        for (int j = 0; j < 4; j++) {                                            \
            int idx = tid + j * 256;                                             \
            int r  = idx >> 3;                                                   \
            int c8 = idx & 7;                                                    \
            int kk = _k0 + c8 * 8;                                               \
            uint32_t dst = sbase + (boff + r * KS + c8 * 8) * 2;                 \
            cp_async16(dst, Bw + (size_t)(m0 + r) * KTOT + kk);                  \
        }                                                                        \
        cp_commit();                                                             \
    } while (0)

#define LOAD_STAGE_A(S, K0)                                                      \
    do {                                                                         \
        const int _k0 = (K0);                                                    \
        const uint32_t aoff = ((S) % NSTAGE) * STG_SZ;                           \
        _Pragma("unroll")                                                        \
        for (int j = 0; j < 4; j++) {                                            \
            int idx = tid + j * 256;                                             \
            int r  = idx >> 3;                                                   \
            int c8 = idx & 7;                                                    \
            int kk = _k0 + c8 * 8;                                               \
            int n = n0 + r;                                                      \
            int t = n & (L_ - 1);                                                \
            int b = n >> 10;                                                     \
            uint32_t dst = sbase + (aoff + r * KS + c8 * 8) * 2;                 \
            if (kk < KHALF) {                                                    \
                if (t == 0) {                                                    \
                    if (INJ) cp_async16_zero(dst, Asrc);                         \
                    else cp_async16(dst, g_z0h + b * H_ + kk);                   \
                } else {                                                         \
                    cp_async16(dst, Asrc + (size_t)(n - 1) * KHALF + kk);        \
                }                                                                \
            } else {                                                             \
                cp_async16(dst, Asrc + (size_t)n * KHALF + (kk - KHALF));        \
            }                                                                    \
        }                                                                        \
        cp_commit();                                                             \
    } while (0)

#define LOAD_STAGE_AB(S, K0)                                                     \
    do {                                                                         \
        const int _k0 = (K0);                                                    \
        const uint32_t aoff = ((S) % NSTAGE) * STG_SZ;                           \
        const uint32_t boff = aoff + STG_A;                                      \
        _Pragma("unroll")                                                        \
        for (int j = 0; j < 4; j++) {                                            \
            int idx = tid + j * 256;                                             \
            int r  = idx >> 3;                                                   \
            int c8 = idx & 7;                                                    \
            int kk = _k0 + c8 * 8;                                               \
            {                                                                    \
                int n = n0 + r;                                                  \
                int t = n & (L_ - 1);                                            \
                int b = n >> 10;                                                 \
                uint32_t dst = sbase + (aoff + r * KS + c8 * 8) * 2;             \
                if (kk < KHALF) {                                                \
                    if (t == 0) {                                                \
                        if (INJ) cp_async16_zero(dst, Asrc);                     \
                        else cp_async16(dst, g_z0h + b * H_ + kk);               \
                    } else {                                                     \
                        cp_async16(dst, Asrc + (size_t)(n - 1) * KHALF + kk);    \
                    }                                                            \
                } else {                                                         \
                    cp_async16(dst, Asrc + (size_t)n * KHALF + (kk - KHALF));    \
                }                                                                \
            }                                                                    \
            {                                                                    \
                uint32_t dst = sbase + (boff + r * KS + c8 * 8) * 2;             \
                cp_async16(dst, Bw + (size_t)(m0 + r) * KTOT + kk);              \
            }                                                                    \
        }                                                                        \
        cp_commit();                                                             \
    } while (0)

    // prefetch weight stages (no h/c dependency), then wait for producers
    LOAD_STAGE_B(0, 0);
    LOAD_STAGE_B(1, BK);
    if (threadIdx.x == 0 && l > 0) {
        int lo = (iblk > 0) ? iblk - 1 : 0;
        int hi = (iblk < NBLK_N - 1) ? iblk + 1 : NBLK_N - 1;
        for (int ii = lo; ii <= hi; ii++)
            while (ld_acquire(&g_cnt[l - 1][ii]) < NBLK_M) __nanosleep(64);
    }
    __syncthreads();
    LOAD_STAGE_A(0, 0);
    LOAD_STAGE_A(1, BK);

    float acc[4][4][4];
#pragma unroll
    for (int i = 0; i < 4; i++)
#pragma unroll
        for (int j = 0; j < 4; j++)
#pragma unroll
            for (int e = 0; e < 4; e++) acc[i][j][e] = 0.0f;

#pragma unroll 1
    for (int kt = 0; kt < NKT; kt++) {
        cp_wait<NSTAGE - 2>();
        __syncthreads();

        const int sf = kt + NSTAGE - 1;
        if (sf < NKT) LOAD_STAGE_AB(sf, sf * BK);
        else cp_commit();

        const uint32_t a_base = sbase + (uint32_t)((kt % NSTAGE) * STG_SZ) * 2;
        const uint32_t b_base = a_base + STG_A * 2;

#pragma unroll
        for (int ks = 0; ks < BK; ks += 16) {
            uint32_t af[4][4];
            uint32_t bf[2][4];
#pragma unroll
            for (int fi = 0; fi < 4; fi++) {
                uint32_t addr = a_base +
                    (uint32_t)((wn + fi * 16 + lrow) * KS + ks + lcol) * 2;
                ldmatrix_x4(af[fi], addr);
            }
#pragma unroll
            for (int fh = 0; fh < 2; fh++) {
                uint32_t addr = b_base +
                    (uint32_t)((wm + fh * 16 + lrow) * KS + ks + lcol) * 2;
                ldmatrix_x4(bf[fh], addr);
            }
#pragma unroll
            for (int fi = 0; fi < 4; fi++) {
#pragma unroll
                for (int fh = 0; fh < 2; fh++) {
#pragma unroll
                    for (int s2 = 0; s2 < 2; s2++) {
                        int fj = fh * 2 + s2;
                        mma_f16(acc[fi][fj][0], acc[fi][fj][1],
                                acc[fi][fj][2], acc[fi][fj][3],
                                af[fi][0], af[fi][1], af[fi][2], af[fi][3],
                                bf[fh][s2], bf[fh][s2 + 2]);
                    }
                }
            }
        }
    }

    // ---------------- epilogue ----------------
    __half* us_s  = smh;
    float*  pre_s = (float*)smh + PRE_OFF;
    const int chbase = m0 / 4;     // mblk * 32

    if (INJ) {
#pragma unroll
        for (int fi = 0; fi < 4; fi++) {
#pragma unroll
            for (int fj = 0; fj < 4; fj++) {
                int n1  = n0 + wn + fi * 16 + grp;
                int col = wm + fj * 8 + qid * 2;
                float b0 = g_bias[m0 + col], b1 = g_bias[m0 + col + 1];
                acc[fi][fj][0] += b0; acc[fi][fj][1] += b1;
                acc[fi][fj][2] += b0; acc[fi][fj][3] += b1;
                *(__half2*)(g_us2 + (size_t)n1 * M4_ + m0 + col) =
                    __floats2half2_rn(acc[fi][fj][0], acc[fi][fj][1]);
                *(__half2*)(g_us2 + (size_t)(n1 + 8) * M4_ + m0 + col) =
                    __floats2half2_rn(acc[fi][fj][2], acc[fi][fj][3]);
            }
        }
#pragma unroll
        for (int p = 0; p < 2; p++) {
            __syncthreads();
            if ((wid >> 2) == p) {
#pragma unroll
                for (int fi = 0; fi < 4; fi++) {
#pragma unroll
                    for (int fj = 0; fj < 4; fj++) {
                        int r0   = fi * 16 + grp;
                        int cidx = wm + fj * 8 + qid * 2;
                        *(float2*)&pre_s[r0 * PS + cidx] =
                            make_float2(acc[fi][fj][0], acc[fi][fj][1]);
                        *(float2*)&pre_s[(r0 + 8) * PS + cidx] =
                            make_float2(acc[fi][fj][2], acc[fi][fj][3]);
                    }
                }
            }
            __syncthreads();
#pragma unroll
            for (int it = 0; it < 2; it++) {
                int row = nl + it * 32;
                int n = n0 + p * 64 + row;
                int t = n & (L_ - 1);
                int b = n >> 10;
                int ch = chbase + q * 4;

                float pi[4], po[4], pg[4], pf[4], cprev[4];
#pragma unroll
                for (int e = 0; e < 4; e++) {
                    pi[e] = pre_s[row * PS + 0 * 32 + q * 4 + e];
                    po[e] = pre_s[row * PS + 1 * 32 + q * 4 + e];
                    pg[e] = pre_s[row * PS + 2 * 32 + q * 4 + e];
                    pf[e] = pre_s[row * PS + 3 * 32 + q * 4 + e];
                    cprev[e] = 0.0f;
                }
                if (t == 0) {
#pragma unroll
                    for (int e = 0; e < 4; e++) {
                        pi[e] += g_pre0[b * M4_ + m0 + 0 * 32 + q * 4 + e];
                        po[e] += g_pre0[b * M4_ + m0 + 1 * 32 + q * 4 + e];
                        pg[e] += g_pre0[b * M4_ + m0 + 2 * 32 + q * 4 + e];
                        pf[e] += g_pre0[b * M4_ + m0 + 3 * 32 + q * 4 + e];
                        cprev[e] = z0[b * (2 * H_) + H_ + ch + e];
                    }
                }
                __half hh[4], cc[4];
#pragma unroll
                for (int e = 0; e < 4; e++) {
                    float si = 1.0f / (1.0f + __expf(-pi[e]));
                    float so = 1.0f / (1.0f + __expf(-po[e]));
                    float sf = 1.0f / (1.0f + __expf(-pf[e]));
                    float tg = tanh_fast(pg[e]);
                    float c = sf * cprev[e] + si * tg;
                    float h = so * tanh_fast(c);
                    hh[e] = __float2half_rn(h);
                    cc[e] = __float2half_rn(c);
                }
                *(__half2*)(g_hh1 + (size_t)n * H_ + ch)     = __halves2half2(hh[0], hh[1]);
                *(__half2*)(g_hh1 + (size_t)n * H_ + ch + 2) = __halves2half2(hh[2], hh[3]);
                *(__half2*)(g_ch1 + (size_t)n * H_ + ch)     = __halves2half2(cc[0], cc[1]);
                *(__half2*)(g_ch1 + (size_t)n * H_ + ch + 2) = __halves2half2(cc[2], cc[3]);
            }
        }
    } else {
        const __half* __restrict__ cpb = rd ? g_ch1 : g_ch0;
        __half* __restrict__ cn  = rd ? g_ch0 : g_ch1;
        __half* __restrict__ hhn = rd ? g_hh0 : g_hh1;

#pragma unroll
        for (int p = 0; p < 2; p++) {
            __syncthreads();
#pragma unroll
            for (int j = 0; j < 4; j++) {
                int id = tid + j * 256;
                int row = id >> 4;
                int c   = id & 15;
                int n = n0 + p * 64 + row;
                cp_async16(sbase + (uint32_t)(row * USS + c * 8) * 2,
                           g_us2 + (size_t)n * M4_ + m0 + c * 8);
            }
            cp_commit();

            if ((wid >> 2) == p) {
#pragma unroll
                for (int fi = 0; fi < 4; fi++) {
#pragma unroll
                    for (int fj = 0; fj < 4; fj++) {
                        int r0   = fi * 16 + grp;
                        int cidx = wm + fj * 8 + qid * 2;
                        *(float2*)&pre_s[r0 * PS + cidx] =
                            make_float2(acc[fi][fj][0], acc[fi][fj][1]);
                        *(float2*)&pre_s[(r0 + 8) * PS + cidx] =
                            make_float2(acc[fi][fj][2], acc[fi][fj][3]);
                    }
                }
            }
            cp_wait<0>();
            __syncthreads();

#pragma unroll
            for (int it = 0; it < 2; it++) {
                int row = nl + it * 32;
                int n = n0 + p * 64 + row;
                int t = n & (L_ - 1);
                int b = n >> 10;
                int ch = chbase + q * 4;

                float4 pi4 = *(const float4*)&pre_s[row * PS + 0 * 32 + q * 4];
                float4 po4 = *(const float4*)&pre_s[row * PS + 1 * 32 + q * 4];
                float4 pg4 = *(const float4*)&pre_s[row * PS + 2 * 32 + q * 4];
                float4 pf4 = *(const float4*)&pre_s[row * PS + 3 * 32 + q * 4];

                const __half* ur = us_s + row * USS + q * 4;
                float2 uiA = __half22float2(*(const __half2*)(ur + 0 * 32));
                float2 uiB = __half22float2(*(const __half2*)(ur + 0 * 32 + 2));
                float2 uoA = __half22float2(*(const __half2*)(ur + 1 * 32));
                float2 uoB = __half22float2(*(const __half2*)(ur + 1 * 32 + 2));
                float2 ugA = __half22float2(*(const __half2*)(ur + 2 * 32));
                float2 ugB = __half22float2(*(const __half2*)(ur + 2 * 32 + 2));
                float2 ufA = __half22float2(*(const __half2*)(ur + 3 * 32));
                float2 ufB = __half22float2(*(const __half2*)(ur + 3 * 32 + 2));
                float ui[4] = {uiA.x, uiA.y, uiB.x, uiB.y};
                float uo[4] = {uoA.x, uoA.y, uoB.x, uoB.y};
                float ug[4] = {ugA.x, ugA.y, ugB.x, ugB.y};
                float uf[4] = {ufA.x, ufA.y, ufB.x, ufB.y};

                float cpl[4];
                if (t == 0) {
                    float4 zc = *(const float4*)(z0 + b * (2 * H_) + H_ + ch);
                    cpl[0] = zc.x; cpl[1] = zc.y; cpl[2] = zc.z; cpl[3] = zc.w;
                } else {
                    float2 cA = __half22float2(*(const __half2*)(cpb + (size_t)(n - 1) * H_ + ch));
                    float2 cB = __half22float2(*(const __half2*)(cpb + (size_t)(n - 1) * H_ + ch + 2));
                    cpl[0] = cA.x; cpl[1] = cA.y; cpl[2] = cB.x; cpl[3] = cB.y;
                }

                const float* pip = (const float*)&pi4;
                const float* pop = (const float*)&po4;
                const float* pgp = (const float*)&pg4;
                const float* pfp = (const float*)&pf4;

                float4 hv, cv;
                float* hvp = (float*)&hv;
                float* cvp = (float*)&cv;
#pragma unroll
                for (int e = 0; e < 4; e++) {
                    float pi = pip[e] + ui[e];
                    float po = pop[e] + uo[e];
                    float pg = pgp[e] + ug[e];
                    float pf = pfp[e] + uf[e];
                    float si = 1.0f / (1.0f + __expf(-pi));
                    float so = 1.0f / (1.0f + __expf(-po));
                    float sf = 1.0f / (1.0f + __expf(-pf));
                    float tg = tanh_fast(pg);
                    float c = sf * cpl[e] + si * tg;
                    float h = so * tanh_fast(c);
                    hvp[e] = h;
                    cvp[e] = c;
                }
                if (last) {
                    if (chbase >= H_ - NOUT_) {
                        *(float4*)(out + (size_t)n * NOUT_ + (ch - (H_ - NOUT_))) = hv;
                    }
                    if (t == L_ - 1) {
                        const size_t tot = (size_t)B_ * L_ * NOUT_;
                        *(float4*)(out + tot + b * (2 * H_) + ch)      = hv;
                        *(float4*)(out + tot + b * (2 * H_) + H_ + ch) = cv;
                    }
                } else {
                    __half2 h01 = __floats2half2_rn(hvp[0], hvp[1]);
                    __half2 h23 = __floats2half2_rn(hvp[2], hvp[3]);
                    __half2 c01 = __floats2half2_rn(cvp[0], cvp[1]);
                    __half2 c23 = __floats2half2_rn(cvp[2], cvp[3]);
                    *(__half2*)(hhn + (size_t)n * H_ + ch)     = h01;
                    *(__half2*)(hhn + (size_t)n * H_ + ch + 2) = h23;
                    *(__half2*)(cn + (size_t)n * H_ + ch)      = c01;
                    *(__half2*)(cn + (size_t)n * H_ + ch + 2)  = c23;
                }
            }
        }
    }

    // publish completion
    __syncthreads();
    if (threadIdx.x == 0) {
        __threadfence();
        atomicAdd(&g_cnt[l][iblk], 1);
    }
#undef LOAD_STAGE_AB
#undef LOAD_STAGE_A
#undef LOAD_STAGE_B
}

// ===========================================================================
// Persistent mega-kernel: ticketed tiles over all 10 layers.
// ===========================================================================
__global__ __launch_bounds__(256, 2)
void gemm_mega(const float* __restrict__ z0, float* __restrict__ out) {
    extern __shared__ __half smh[];
    __shared__ unsigned sm_w;
    const uint32_t sbase = smem_u32(smh);

    for (;;) {
        if (threadIdx.x == 0) sm_w = atomicAdd(&g_ticket, 1u);
        __syncthreads();
        const unsigned w = sm_w;
        if (w >= TOTAL_ITEMS) return;

        const int l    = w / ITEMS_PER_LAYER;
        const int r_   = w - l * ITEMS_PER_LAYER;
        const int iblk = r_ / NBLK_M;
        const int mblk = r_ - iblk * NBLK_M;
        const int n0 = iblk * 128;
        const int m0 = mblk * 128;

        if (l == 0)
            do_tile<KI_, true>(smh, sbase, z0, out, n0, m0, iblk, l, false, 0);
        else
            do_tile<KC_, false>(smh, sbase, z0, out, n0, m0, iblk, l,
                                l == NLAYER_ - 1, l & 1);
    }
}

// ===========================================================================
extern "C" void kernel_launch(void* const* d_in, const int* in_sizes, int n_in,
                              void* d_out, int out_size) {
    const float* X        = (const float*)d_in[0];
    const float* z0       = (const float*)d_in[1];
    const float* inject_w = (const float*)d_in[2];
    const float* inject_b = (const float*)d_in[3];
    const float* conv_w   = (const float*)d_in[4];
    const float* conv_b   = (const float*)d_in[5];
    float* out = (float*)d_out;

    cudaFuncSetAttribute(gemm_mega,
                         cudaFuncAttributeMaxDynamicSharedMemorySize, SMEM_BYTES);

    prep_fused<<<PREP_TOTAL, 256>>>(X, z0, inject_w, inject_b, conv_b, conv_w);
    gemm_mega<<<GRID_PERSIST, 256, SMEM_BYTES>>>(z0, out);
}